// round 12
// baseline (speedup 1.0000x reference)
#include <cuda_runtime.h>
#include <cuda_fp16.h>
#include <math.h>
#include <stdint.h>

// Problem constants
#define DMODEL 1024
#define MTOK   8192      // B*S
#define FFDIM  4096
#define NHEAD  16
#define HDIM   64
#define SEQ    1024
#define BATCH  8

#define STAGE_BYTES 20480            // A: 128x80B + B: 128x80B (fp16, stride 40)
#define GEMM_DSMEM  (3 * STAGE_BYTES)
#define M1 (1024 * 1024)

// ---------------- scratch (device globals) ---------------------------------------
__device__ __half g_h  [MTOK * DMODEL];   // LN out (both blocks)
__device__ __half g_q  [MTOK * DMODEL];
__device__ __half g_k  [MTOK * DMODEL];
__device__ __half g_v  [MTOK * DMODEL];
__device__ __half g_ctx[MTOK * DMODEL];
__device__ float  g_x2 [MTOK * DMODEL];   // residual stream after attention (fp32)
__device__ __half g_act[MTOK * FFDIM];
// fp16 transposed weights W^T [N][K]: [0:Wq][1M:Wk][2M:Wv][3M:Wo][4M:W1][8M:W2]
__device__ __half g_wc[12 * M1];

// ---------------- helpers ---------------------------------------------------------
__device__ __forceinline__ uint32_t pack2(float a, float b) {
    __half2 h = __floats2half2_rn(a, b);
    return *reinterpret_cast<uint32_t*>(&h);
}

// fast exp on fma pipe (softmax args <= 0); rel err ~2e-6
__device__ __forceinline__ float fexp(float x) {
    x = fmaxf(x, -80.0f);
    const float y = x * 1.4426950408889634f;
    const float t = y + 12582912.0f;
    const int   n = __float_as_int(t) - 0x4B400000;
    const float f = y - (t - 12582912.0f);
    float p =          1.3333558e-3f;
    p = fmaf(p, f, 9.6181291e-3f);
    p = fmaf(p, f, 5.5504109e-2f);
    p = fmaf(p, f, 2.4022651e-1f);
    p = fmaf(p, f, 6.9314718e-1f);
    p = fmaf(p, f, 1.0f);
    return p * __int_as_float((n + 127) << 23);
}

__device__ __forceinline__ void mma_f16(float* d, const uint32_t* a, const uint32_t* b) {
    asm volatile(
        "mma.sync.aligned.m16n8k16.row.col.f32.f16.f16.f32 "
        "{%0,%1,%2,%3}, {%4,%5,%6,%7}, {%8,%9}, {%0,%1,%2,%3};"
        : "+f"(d[0]), "+f"(d[1]), "+f"(d[2]), "+f"(d[3])
        : "r"(a[0]), "r"(a[1]), "r"(a[2]), "r"(a[3]), "r"(b[0]), "r"(b[1]));
}

__device__ __forceinline__ uint32_t smem_u32(const void* p) {
    uint32_t a;
    asm("{ .reg .u64 t; cvta.to.shared.u64 t, %1; cvt.u32.u64 %0, t; }" : "=r"(a) : "l"(p));
    return a;
}

__device__ __forceinline__ void cpa16(uint32_t dst, const void* src) {
    asm volatile("cp.async.cg.shared.global [%0], [%1], 16;" :: "r"(dst), "l"(src));
}
#define CP_COMMIT() asm volatile("cp.async.commit_group;" ::: "memory")
#define CP_WAIT1()  asm volatile("cp.async.wait_group 1;" ::: "memory")
#define CP_WAIT0()  asm volatile("cp.async.wait_group 0;" ::: "memory")

#define LDMATRIX_X4(r0, r1, r2, r3, addr) \
    asm volatile("ldmatrix.sync.aligned.m8n8.x4.shared.b16 {%0,%1,%2,%3}, [%4];" \
        : "=r"(r0), "=r"(r1), "=r"(r2), "=r"(r3) : "r"(addr))
#define LDMATRIX_X4_T(r0, r1, r2, r3, addr) \
    asm volatile("ldmatrix.sync.aligned.m8n8.x4.trans.shared.b16 {%0,%1,%2,%3}, [%4];" \
        : "=r"(r0), "=r"(r1), "=r"(r2), "=r"(r3) : "r"(addr))

// ---------------- weight convert + transpose: W[K][N] f32 -> W^T[N][K] fp16 -------
__global__ __launch_bounds__(256) void wconv_kernel(
    const float* __restrict__ Wq, const float* __restrict__ Wk,
    const float* __restrict__ Wv, const float* __restrict__ Wo,
    const float* __restrict__ W1, const float* __restrict__ W2) {
    size_t t = (size_t)blockIdx.x * 256 + threadIdx.x;   // 1.5M threads, 8 elems each
    const float* src;
    size_t base; int K, N;
    if      (t <  128 * 1024) { src = Wq; base = 0;       K = 1024; N = 1024; }
    else if (t <  256 * 1024) { src = Wk; base = 1 * M1;  K = 1024; N = 1024; t -= 128 * 1024; }
    else if (t <  384 * 1024) { src = Wv; base = 2 * M1;  K = 1024; N = 1024; t -= 256 * 1024; }
    else if (t <  512 * 1024) { src = Wo; base = 3 * M1;  K = 1024; N = 1024; t -= 384 * 1024; }
    else if (t < 1024 * 1024) { src = W1; base = 4 * M1;  K = 1024; N = 4096; t -= 512 * 1024; }
    else                      { src = W2; base = 8 * M1;  K = 4096; N = 1024; t -= 1024 * 1024; }
    const int n  = (int)(t % N);          // lanes -> consecutive n: coalesced reads
    const int kb = (int)(t / N) * 8;
    __half2 h[4];
#pragma unroll
    for (int i = 0; i < 4; i++) {
        const float a = src[(size_t)(kb + 2 * i) * N + n];
        const float b = src[(size_t)(kb + 2 * i + 1) * N + n];
        h[i] = __floats2half2_rn(a, b);
    }
    *(uint4*)(g_wc + base + (size_t)n * K + kb) = *(uint4*)h;
}

// ---------------- LayerNorm: fp32 in -> fp16 out ----------------------------------
template <int SRC>   // 0: external x, 1: g_x2
__global__ __launch_bounds__(256) void ln_kernel(const float* __restrict__ xext,
                                                 const float* __restrict__ g,
                                                 const float* __restrict__ be) {
    const float* src = SRC ? g_x2 : xext;
    __shared__ float s1[256], s2[256];
    const int row = blockIdx.x;
    const int tid = threadIdx.x;
    const float4 v = ((const float4*)(src + (size_t)row * DMODEL))[tid];
    float sum = v.x + v.y + v.z + v.w;
    float sq  = v.x*v.x + v.y*v.y + v.z*v.z + v.w*v.w;
    s1[tid] = sum; s2[tid] = sq;
    __syncthreads();
    for (int s = 128; s > 0; s >>= 1) {
        if (tid < s) { s1[tid] += s1[tid + s]; s2[tid] += s2[tid + s]; }
        __syncthreads();
    }
    const float mean = s1[0] * (1.0f / DMODEL);
    const float var  = s2[0] * (1.0f / DMODEL) - mean * mean;
    const float rs   = rsqrtf(var + 1e-5f);
    const float4 gv = ((const float4*)g)[tid];
    const float4 bv = ((const float4*)be)[tid];
    uint2 o;
    o.x = pack2((v.x - mean) * rs * gv.x + bv.x, (v.y - mean) * rs * gv.y + bv.y);
    o.y = pack2((v.z - mean) * rs * gv.z + bv.z, (v.w - mean) * rs * gv.w + bv.w);
    *(uint2*)(g_h + (size_t)row * DMODEL + tid * 4) = o;
}

// ---------------- Dense GEMM: fp16 m16n8k16 + cp.async 3-stage --------------------
// MODE 0: QKV (z selects W/bias/dst, half out)      MODE 1: AO (x2 fp32 out, res x)
// MODE 2: FFN1 (GELU, half out)                     MODE 3: FFN2 (fp32 out, res x2)
// Tile 128x128, BK=32, 8 warps (2m x 4n), warp 64x32. smem stride 80B (conflict-free).
template <int MODE>
__global__ __launch_bounds__(256) void gemm_h_kernel(
    const float* __restrict__ ba, const float* __restrict__ bb2, const float* __restrict__ bc,
    float* __restrict__ extC, const float* __restrict__ extRes) {
    extern __shared__ __align__(16) char dsm[];
    constexpr int N = (MODE == 2) ? 4096 : 1024;
    constexpr int K = (MODE == 3) ? 4096 : 1024;

    const __half* A = (MODE == 0 || MODE == 2) ? g_h : (MODE == 1 ? g_ctx : g_act);
    const int z = (MODE == 0) ? blockIdx.z : 0;
    const __half* W = g_wc + (MODE == 0 ? (size_t)z * M1
                             : MODE == 1 ? (size_t)3 * M1
                             : MODE == 2 ? (size_t)4 * M1 : (size_t)8 * M1);
    const float* bias = (MODE == 0) ? (z == 0 ? ba : (z == 1 ? bb2 : bc)) : ba;
    __half* Ch = (MODE == 0) ? (z == 0 ? g_q : (z == 1 ? g_k : g_v))
               : (MODE == 2) ? g_act : nullptr;
    float* Cf = (MODE == 1) ? g_x2 : (MODE == 3) ? extC : nullptr;
    const float* R = (MODE == 1) ? extRes : (MODE == 3) ? g_x2 : nullptr;

    const int tid  = threadIdx.x;
    const int lane = tid & 31;
    const int wid  = tid >> 5;
    const int mw0  = (wid >> 2) * 64;
    const int nw0  = (wid & 3) * 32;
    const int rowBase = blockIdx.y * 128;
    const int colBase = blockIdx.x * 128;
    const uint32_t dsmb = smem_u32(dsm);

    // staging: A/B each 128 rows x 4 chunks(16B); thread -> row tid>>1, 2 chunks
    const int srow = tid >> 1;
    const int sch  = (tid & 1) * 2;
    const __half* Asrc = A + (size_t)(rowBase + srow) * K + sch * 8;
    const __half* Bsrc = W + (size_t)(colBase + srow) * K + sch * 8;
    const uint32_t adst = srow * 80 + sch * 16;
    const uint32_t bdst = 10240 + srow * 80 + sch * 16;

    float acc[4][4][4];
#pragma unroll
    for (int i = 0; i < 4; i++)
#pragma unroll
        for (int j = 0; j < 4; j++)
#pragma unroll
            for (int c = 0; c < 4; c++) acc[i][j][c] = 0.0f;

    auto issue = [&](int s, int c) {
        const uint32_t st = dsmb + s * STAGE_BYTES;
        const size_t k0 = (size_t)c << 5;
        cpa16(st + adst,      Asrc + k0);
        cpa16(st + adst + 16, Asrc + k0 + 8);
        cpa16(st + bdst,      Bsrc + k0);
        cpa16(st + bdst + 16, Bsrc + k0 + 8);
    };

    issue(0, 0); CP_COMMIT();
    issue(1, 1); CP_COMMIT();

    const int nkt = K >> 5;
    for (int kt = 0; kt < nkt; kt++) {
        CP_WAIT1();
        __syncthreads();
        const int s = kt % 3;
        const uint32_t ab = dsmb + s * STAGE_BYTES;
        const uint32_t bb = ab + 10240;

#pragma unroll
        for (int sub = 0; sub < 2; sub++) {
            uint32_t a[4][4];
#pragma unroll
            for (int i = 0; i < 4; i++) {
                const uint32_t addr = ab + (mw0 + i * 16 + (lane & 15)) * 80
                                    + (2 * sub + (lane >> 4)) * 16;
                LDMATRIX_X4(a[i][0], a[i][1], a[i][2], a[i][3], addr);
            }
            uint32_t bf[2][4];   // bf[jp]: r0=j_even b0, r1=j_odd b0, r2=j_even b1, r3=j_odd b1
#pragma unroll
            for (int jp = 0; jp < 2; jp++) {
                const uint32_t addr = bb + (nw0 + 16 * jp + (lane & 15)) * 80
                                    + (2 * sub + (lane >> 4)) * 16;
                LDMATRIX_X4(bf[jp][0], bf[jp][1], bf[jp][2], bf[jp][3], addr);
            }
#pragma unroll
            for (int j = 0; j < 4; j++) {
                uint32_t bfr[2] = { bf[j >> 1][j & 1], bf[j >> 1][(j & 1) + 2] };
#pragma unroll
                for (int i = 0; i < 4; i++)
                    mma_f16(acc[i][j], a[i], bfr);
            }
        }

        if (kt + 2 < nkt) issue((kt + 2) % 3, kt + 2);
        CP_COMMIT();
    }

    // epilogue
    const int lr = lane >> 2;
    const int lc = lane & 3;
#pragma unroll
    for (int i = 0; i < 4; i++) {
        const int r0 = rowBase + mw0 + i * 16 + lr;
#pragma unroll
        for (int j = 0; j < 4; j++) {
            const int c0 = colBase + nw0 + j * 8 + 2 * lc;
            const float b0v = bias[c0], b1v = bias[c0 + 1];
            float v00 = acc[i][j][0] + b0v;
            float v01 = acc[i][j][1] + b1v;
            float v10 = acc[i][j][2] + b0v;
            float v11 = acc[i][j][3] + b1v;
            if (MODE == 2) {
                v00 = 0.5f * v00 * (1.0f + erff(v00 * 0.70710678118654752f));
                v01 = 0.5f * v01 * (1.0f + erff(v01 * 0.70710678118654752f));
                v10 = 0.5f * v10 * (1.0f + erff(v10 * 0.70710678118654752f));
                v11 = 0.5f * v11 * (1.0f + erff(v11 * 0.70710678118654752f));
            }
            if (MODE == 0 || MODE == 2) {
                *(uint32_t*)(Ch + (size_t)r0 * N + c0)       = pack2(v00, v01);
                *(uint32_t*)(Ch + (size_t)(r0 + 8) * N + c0) = pack2(v10, v11);
            } else {
                const float2 r0v = *(const float2*)(R + (size_t)r0 * N + c0);
                const float2 r1v = *(const float2*)(R + (size_t)(r0 + 8) * N + c0);
                float2 o0; o0.x = v00 + r0v.x; o0.y = v01 + r0v.y;
                float2 o1; o1.x = v10 + r1v.x; o1.y = v11 + r1v.y;
                *(float2*)(Cf + (size_t)r0 * N + c0) = o0;
                *(float2*)(Cf + (size_t)(r0 + 8) * N + c0) = o1;
            }
        }
    }
}

// ---------------- Flash attention: fp16 m16n8k16, cp.async, register P ------------
// Grid (SEQ/64, BATCH*NHEAD), 128 thr = 4 warps; warp owns 16 q-rows.
// K/V staged fp16 (stride 144B), 2-stage cp.async, 1 sync/tile.
// P built from S fragments in registers (FA2 trick). V via ldmatrix.trans.
__global__ __launch_bounds__(128) void fa_kernel() {
    __shared__ __align__(16) char fsm[2 * 18432];   // per stage: K 9216B + V 9216B
    const uint32_t fab = smem_u32(fsm);

    const int bh = blockIdx.y;
    const int b  = bh >> 4, h = bh & 15;
    const int qBase = blockIdx.x * 64;
    const int tid  = threadIdx.x;
    const int lane = tid & 31;
    const int w    = tid >> 5;
    const int lr   = lane >> 2;
    const int lc   = lane & 3;
    const int qrow = qBase + w * 16;

    const __half* qb = g_q + (size_t)b * SEQ * DMODEL + h * HDIM;
    const __half* kb = g_k + (size_t)b * SEQ * DMODEL + h * HDIM;
    const __half* vb = g_v + (size_t)b * SEQ * DMODEL + h * HDIM;

    // persistent Q fragments (scale 0.125 folded; exact in fp16)
    const __half2 s8 = __float2half2_rn(0.125f);
    uint32_t aq[4][4];
#pragma unroll
    for (int s = 0; s < 4; s++) {
        const __half* p0 = qb + (size_t)(qrow + lr) * DMODEL + s * 16 + 2 * lc;
        const __half* p1 = qb + (size_t)(qrow + lr + 8) * DMODEL + s * 16 + 2 * lc;
        __half2 x0 = __hmul2(*(const __half2*)p0, s8);
        __half2 x1 = __hmul2(*(const __half2*)p1, s8);
        __half2 x2 = __hmul2(*(const __half2*)(p0 + 8), s8);
        __half2 x3 = __hmul2(*(const __half2*)(p1 + 8), s8);
        aq[s][0] = *(uint32_t*)&x0; aq[s][1] = *(uint32_t*)&x1;
        aq[s][2] = *(uint32_t*)&x2; aq[s][3] = *(uint32_t*)&x3;
    }

    auto issue = [&](int kt2) {
        const uint32_t st = fab + (kt2 & 1) * 18432;
        const __half* kbt = kb + (size_t)kt2 * 64 * DMODEL;
        const __half* vbt = vb + (size_t)kt2 * 64 * DMODEL;
#pragma unroll
        for (int i = 0; i < 4; i++) {
            const int c = tid + 128 * i;        // 512 chunks each for K and V
            const int r = c >> 3, ch = c & 7;
            cpa16(st + r * 144 + ch * 16,        kbt + (size_t)r * DMODEL + ch * 8);
            cpa16(st + 9216 + r * 144 + ch * 16, vbt + (size_t)r * DMODEL + ch * 8);
        }
    };

    float m0 = -INFINITY, m1 = -INFINITY, l0 = 0.0f, l1 = 0.0f;
    float oacc[8][4];
#pragma unroll
    for (int j = 0; j < 8; j++)
#pragma unroll
        for (int c = 0; c < 4; c++) oacc[j][c] = 0.0f;

    issue(0); CP_COMMIT();

    for (int kt = 0; kt < SEQ / 64; kt++) {
        CP_WAIT0();
        __syncthreads();
        if (kt + 1 < SEQ / 64) { issue(kt + 1); CP_COMMIT(); }
        const uint32_t ksb = fab + (kt & 1) * 18432;
        const uint32_t vsb = ksb + 9216;

        // S = Q @ K^T (scaled)
        float sacc[8][4];
#pragma unroll
        for (int j = 0; j < 8; j++)
#pragma unroll
            for (int c = 0; c < 4; c++) sacc[j][c] = 0.0f;
#pragma unroll
        for (int j = 0; j < 8; j++) {
            uint32_t bk[8];
#pragma unroll
            for (int sp = 0; sp < 2; sp++) {
                const uint32_t addr = ksb + (8 * j + (lane & 7)) * 144
                                    + (4 * sp + (lane >> 3)) * 16;
                LDMATRIX_X4(bk[sp * 4], bk[sp * 4 + 1], bk[sp * 4 + 2], bk[sp * 4 + 3], addr);
            }
#pragma unroll
            for (int s = 0; s < 4; s++)
                mma_f16(sacc[j], aq[s], &bk[s * 2]);
        }

        // online softmax (rows lr / lr+8; quad shuffles)
        float t0 = -INFINITY, t1 = -INFINITY;
#pragma unroll
        for (int j = 0; j < 8; j++) {
            t0 = fmaxf(t0, fmaxf(sacc[j][0], sacc[j][1]));
            t1 = fmaxf(t1, fmaxf(sacc[j][2], sacc[j][3]));
        }
        t0 = fmaxf(t0, __shfl_xor_sync(0xffffffffu, t0, 1));
        t0 = fmaxf(t0, __shfl_xor_sync(0xffffffffu, t0, 2));
        t1 = fmaxf(t1, __shfl_xor_sync(0xffffffffu, t1, 1));
        t1 = fmaxf(t1, __shfl_xor_sync(0xffffffffu, t1, 2));
        const float nm0 = fmaxf(m0, t0);
        const float nm1 = fmaxf(m1, t1);
        const float al0 = fexp(m0 - nm0);
        const float al1 = fexp(m1 - nm1);
        m0 = nm0; m1 = nm1;
        float s0 = 0.0f, s1 = 0.0f;
#pragma unroll
        for (int j = 0; j < 8; j++) {
            sacc[j][0] = fexp(sacc[j][0] - m0);
            sacc[j][1] = fexp(sacc[j][1] - m0);
            sacc[j][2] = fexp(sacc[j][2] - m1);
            sacc[j][3] = fexp(sacc[j][3] - m1);
            s0 += sacc[j][0] + sacc[j][1];
            s1 += sacc[j][2] + sacc[j][3];
        }
        s0 += __shfl_xor_sync(0xffffffffu, s0, 1);
        s0 += __shfl_xor_sync(0xffffffffu, s0, 2);
        s1 += __shfl_xor_sync(0xffffffffu, s1, 1);
        s1 += __shfl_xor_sync(0xffffffffu, s1, 2);
        l0 = l0 * al0 + s0;
        l1 = l1 * al1 + s1;
#pragma unroll
        for (int j = 0; j < 8; j++) {
            oacc[j][0] *= al0; oacc[j][1] *= al0;
            oacc[j][2] *= al1; oacc[j][3] *= al1;
        }

        // P fragments directly from S fragments (no smem round-trip)
        uint32_t ap[4][4];
#pragma unroll
        for (int s = 0; s < 4; s++) {
            ap[s][0] = pack2(sacc[2 * s][0], sacc[2 * s][1]);
            ap[s][1] = pack2(sacc[2 * s][2], sacc[2 * s][3]);
            ap[s][2] = pack2(sacc[2 * s + 1][0], sacc[2 * s + 1][1]);
            ap[s][3] = pack2(sacc[2 * s + 1][2], sacc[2 * s + 1][3]);
        }

        // O += P @ V ; V fragments via ldmatrix.trans on [key][hd]
#pragma unroll
        for (int s = 0; s < 4; s++) {
#pragma unroll
            for (int jp = 0; jp < 4; jp++) {
                uint32_t bv4[4];
                const uint32_t addr = vsb + (16 * s + (lane & 15)) * 144
                                    + (2 * jp + (lane >> 4)) * 16;
                LDMATRIX_X4_T(bv4[0], bv4[1], bv4[2], bv4[3], addr);
                mma_f16(oacc[2 * jp],     ap[s], &bv4[0]);
                mma_f16(oacc[2 * jp + 1], ap[s], &bv4[2]);
            }
        }
    }

    // epilogue: normalize, store ctx fp16
    const float inv0 = 1.0f / l0;
    const float inv1 = 1.0f / l1;
    __half* crow0 = g_ctx + (size_t)(b * SEQ + qrow + lr) * DMODEL + h * HDIM;
    __half* crow1 = g_ctx + (size_t)(b * SEQ + qrow + lr + 8) * DMODEL + h * HDIM;
#pragma unroll
    for (int j = 0; j < 8; j++) {
        *(uint32_t*)(crow0 + j * 8 + 2 * lc) = pack2(oacc[j][0] * inv0, oacc[j][1] * inv0);
        *(uint32_t*)(crow1 + j * 8 + 2 * lc) = pack2(oacc[j][2] * inv1, oacc[j][3] * inv1);
    }
}

// ---------------- launcher -------------------------------------------------------
extern "C" void kernel_launch(void* const* d_in, const int* in_sizes, int n_in,
                              void* d_out, int out_size) {
    const float* x   = (const float*)d_in[0];
    const float* Wq  = (const float*)d_in[1];
    const float* bq  = (const float*)d_in[2];
    const float* Wk  = (const float*)d_in[3];
    const float* bk  = (const float*)d_in[4];
    const float* Wv  = (const float*)d_in[5];
    const float* bv  = (const float*)d_in[6];
    const float* Wo  = (const float*)d_in[7];
    const float* bo  = (const float*)d_in[8];
    const float* W1  = (const float*)d_in[9];
    const float* b1  = (const float*)d_in[10];
    const float* W2  = (const float*)d_in[11];
    const float* b2  = (const float*)d_in[12];
    const float* g1  = (const float*)d_in[13];
    const float* be1 = (const float*)d_in[14];
    const float* g2  = (const float*)d_in[15];
    const float* be2 = (const float*)d_in[16];
    float* out = (float*)d_out;

    cudaFuncSetAttribute(gemm_h_kernel<0>, cudaFuncAttributeMaxDynamicSharedMemorySize, GEMM_DSMEM);
    cudaFuncSetAttribute(gemm_h_kernel<1>, cudaFuncAttributeMaxDynamicSharedMemorySize, GEMM_DSMEM);
    cudaFuncSetAttribute(gemm_h_kernel<2>, cudaFuncAttributeMaxDynamicSharedMemorySize, GEMM_DSMEM);
    cudaFuncSetAttribute(gemm_h_kernel<3>, cudaFuncAttributeMaxDynamicSharedMemorySize, GEMM_DSMEM);

    const dim3 gQKV(DMODEL / 128, MTOK / 128, 3);
    const dim3 gD(DMODEL / 128, MTOK / 128);
    const dim3 gF(FFDIM / 128, MTOK / 128);

    wconv_kernel<<<6144, 256>>>(Wq, Wk, Wv, Wo, W1, W2);

    // --- attention block ---
    ln_kernel<0><<<MTOK, 256>>>(x, g1, be1);                                   // h (fp16)
    gemm_h_kernel<0><<<gQKV, 256, GEMM_DSMEM>>>(bq, bk, bv, nullptr, nullptr); // q,k,v (fp16)
    fa_kernel<<<dim3(SEQ / 64, BATCH * NHEAD), 128>>>();                       // ctx (fp16)
    gemm_h_kernel<1><<<gD, 256, GEMM_DSMEM>>>(bo, bo, bo, nullptr, (float*)x); // x2 (fp32)

    // --- FFN block ---
    ln_kernel<1><<<MTOK, 256>>>(nullptr, g2, be2);                             // h (fp16)
    gemm_h_kernel<2><<<gF, 256, GEMM_DSMEM>>>(b1, b1, b1, nullptr, nullptr);   // act (fp16)
    gemm_h_kernel<3><<<gD, 256, GEMM_DSMEM>>>(b2, b2, b2, out, nullptr);       // out (fp32)
}

// round 13
// speedup vs baseline: 1.1896x; 1.1896x over previous
#include <cuda_runtime.h>
#include <cuda_fp16.h>
#include <math.h>
#include <stdint.h>

// Problem constants
#define DMODEL 1024
#define MTOK   8192      // B*S
#define FFDIM  4096
#define NHEAD  16
#define HDIM   64
#define SEQ    1024
#define BATCH  8

#define STAGE_BYTES 18944            // A: 128x20 f32 (10240B) + B: 16x136 f32 (8704B)
#define GEMM_DSMEM  (3 * STAGE_BYTES)
#define M1 (1024 * 1024)

// ---------------- scratch (device globals) ---------------------------------------
__device__ float  g_h  [MTOK * DMODEL];   // LN out (tf32-rounded fp32)
__device__ __half g_qh [MTOK * DMODEL];
__device__ __half g_kh [MTOK * DMODEL];
__device__ __half g_vh [MTOK * DMODEL];
__device__ float  g_ctx[MTOK * DMODEL];   // FA out (tf32-rounded fp32)
__device__ float  g_x2 [MTOK * DMODEL];   // residual stream after attention (fp32)
__device__ float  g_act[MTOK * FFDIM];    // FFN intermediate (tf32-rounded fp32)
// tf32-rounded fp32 weights: [0:Wq][1M:Wk][2M:Wv][3M:Wo][4M:W1][8M:W2]
__device__ float  g_wc[12 * M1];

// ---------------- helpers ---------------------------------------------------------
__device__ __forceinline__ uint32_t f2tf32(float x) {
    uint32_t r;
    asm("cvt.rna.tf32.f32 %0, %1;" : "=r"(r) : "f"(x));
    return r;
}
__device__ __forceinline__ float roundtf(float x) {
    return __uint_as_float(f2tf32(x));
}
__device__ __forceinline__ uint32_t pack2(float a, float b) {
    __half2 h = __floats2half2_rn(a, b);
    return *reinterpret_cast<uint32_t*>(&h);
}

// fast exp on fma pipe (softmax args <= 0); rel err ~2e-6
__device__ __forceinline__ float fexp(float x) {
    x = fmaxf(x, -80.0f);
    const float y = x * 1.4426950408889634f;
    const float t = y + 12582912.0f;
    const int   n = __float_as_int(t) - 0x4B400000;
    const float f = y - (t - 12582912.0f);
    float p =          1.3333558e-3f;
    p = fmaf(p, f, 9.6181291e-3f);
    p = fmaf(p, f, 5.5504109e-2f);
    p = fmaf(p, f, 2.4022651e-1f);
    p = fmaf(p, f, 6.9314718e-1f);
    p = fmaf(p, f, 1.0f);
    return p * __int_as_float((n + 127) << 23);
}

__device__ __forceinline__ void mma_tf32(float* d, const uint32_t* a, const uint32_t* b) {
    asm volatile(
        "mma.sync.aligned.m16n8k8.row.col.f32.tf32.tf32.f32 "
        "{%0,%1,%2,%3}, {%4,%5,%6,%7}, {%8,%9}, {%0,%1,%2,%3};"
        : "+f"(d[0]), "+f"(d[1]), "+f"(d[2]), "+f"(d[3])
        : "r"(a[0]), "r"(a[1]), "r"(a[2]), "r"(a[3]), "r"(b[0]), "r"(b[1]));
}
__device__ __forceinline__ void mma_f16(float* d, const uint32_t* a, const uint32_t* b) {
    asm volatile(
        "mma.sync.aligned.m16n8k16.row.col.f32.f16.f16.f32 "
        "{%0,%1,%2,%3}, {%4,%5,%6,%7}, {%8,%9}, {%0,%1,%2,%3};"
        : "+f"(d[0]), "+f"(d[1]), "+f"(d[2]), "+f"(d[3])
        : "r"(a[0]), "r"(a[1]), "r"(a[2]), "r"(a[3]), "r"(b[0]), "r"(b[1]));
}

__device__ __forceinline__ uint32_t smem_u32(const void* p) {
    uint32_t a;
    asm("{ .reg .u64 t; cvta.to.shared.u64 t, %1; cvt.u32.u64 %0, t; }" : "=r"(a) : "l"(p));
    return a;
}
__device__ __forceinline__ void cpa16(uint32_t dst, const void* src) {
    asm volatile("cp.async.cg.shared.global [%0], [%1], 16;" :: "r"(dst), "l"(src));
}
#define CP_COMMIT() asm volatile("cp.async.commit_group;" ::: "memory")
#define CP_WAIT1()  asm volatile("cp.async.wait_group 1;" ::: "memory")
#define CP_WAIT0()  asm volatile("cp.async.wait_group 0;" ::: "memory")

#define LDMATRIX_X4(r0, r1, r2, r3, addr) \
    asm volatile("ldmatrix.sync.aligned.m8n8.x4.shared.b16 {%0,%1,%2,%3}, [%4];" \
        : "=r"(r0), "=r"(r1), "=r"(r2), "=r"(r3) : "r"(addr))
#define LDMATRIX_X4_T(r0, r1, r2, r3, addr) \
    asm volatile("ldmatrix.sync.aligned.m8n8.x4.trans.shared.b16 {%0,%1,%2,%3}, [%4];" \
        : "=r"(r0), "=r"(r1), "=r"(r2), "=r"(r3) : "r"(addr))

// ---------------- weight pre-round (fp32 tf32-rounded, no transpose) --------------
__global__ __launch_bounds__(256) void wconv_kernel(
    const float* __restrict__ Wq, const float* __restrict__ Wk,
    const float* __restrict__ Wv, const float* __restrict__ Wo,
    const float* __restrict__ W1, const float* __restrict__ W2) {
    const size_t i4 = ((size_t)blockIdx.x * 256 + threadIdx.x) * 4;
    const float* src;
    size_t base;
    if      (i4 < 1 * M1) { src = Wq; base = 0; }
    else if (i4 < 2 * M1) { src = Wk; base = 1 * M1; }
    else if (i4 < 3 * M1) { src = Wv; base = 2 * M1; }
    else if (i4 < 4 * M1) { src = Wo; base = 3 * M1; }
    else if (i4 < 8 * M1) { src = W1; base = 4 * M1; }
    else                  { src = W2; base = 8 * M1; }
    float4 v = *(const float4*)(src + (i4 - base));
    v.x = roundtf(v.x); v.y = roundtf(v.y); v.z = roundtf(v.z); v.w = roundtf(v.w);
    *(float4*)(g_wc + i4) = v;
}

// ---------------- LayerNorm: fp32 in -> tf32-rounded fp32 out (g_h) ---------------
template <int SRC>   // 0: external x, 1: g_x2
__global__ __launch_bounds__(256) void ln_kernel(const float* __restrict__ xext,
                                                 const float* __restrict__ g,
                                                 const float* __restrict__ be) {
    const float* src = SRC ? g_x2 : xext;
    __shared__ float s1[256], s2[256];
    const int row = blockIdx.x;
    const int tid = threadIdx.x;
    const float4 v = ((const float4*)(src + (size_t)row * DMODEL))[tid];
    float sum = v.x + v.y + v.z + v.w;
    float sq  = v.x*v.x + v.y*v.y + v.z*v.z + v.w*v.w;
    s1[tid] = sum; s2[tid] = sq;
    __syncthreads();
    for (int s = 128; s > 0; s >>= 1) {
        if (tid < s) { s1[tid] += s1[tid + s]; s2[tid] += s2[tid + s]; }
        __syncthreads();
    }
    const float mean = s1[0] * (1.0f / DMODEL);
    const float var  = s2[0] * (1.0f / DMODEL) - mean * mean;
    const float rs   = rsqrtf(var + 1e-5f);
    const float4 gv = ((const float4*)g)[tid];
    const float4 bv = ((const float4*)be)[tid];
    float4 o;
    o.x = roundtf((v.x - mean) * rs * gv.x + bv.x);
    o.y = roundtf((v.y - mean) * rs * gv.y + bv.y);
    o.z = roundtf((v.z - mean) * rs * gv.z + bv.z);
    o.w = roundtf((v.w - mean) * rs * gv.w + bv.w);
    ((float4*)(g_h + (size_t)row * DMODEL))[tid] = o;
}

// ---------------- Dense GEMM: tf32 mma.sync + cp.async 3-stage (round-10 core) ----
// MODE 0: QKV (z selects W/bias/dst; fp16 out)   MODE 1: AO (fp32 x2, res ext x)
// MODE 2: FFN1 (GELU, tf32-rounded fp32 out)     MODE 3: FFN2 (fp32 ext out, res x2)
template <int MODE>
__global__ __launch_bounds__(256) void gemm_cp_kernel(
    const float* __restrict__ ba, const float* __restrict__ bb2, const float* __restrict__ bc,
    float* __restrict__ extC, const float* __restrict__ extRes) {
    extern __shared__ __align__(16) char dsm[];
    constexpr int N = (MODE == 2) ? 4096 : 1024;
    constexpr int K = (MODE == 3) ? 4096 : 1024;

    const float* A = (MODE == 0 || MODE == 2) ? g_h : (MODE == 1 ? g_ctx : g_act);
    const int z = (MODE == 0) ? blockIdx.z : 0;
    const float* W = g_wc + (MODE == 0 ? (size_t)z * M1
                            : MODE == 1 ? (size_t)3 * M1
                            : MODE == 2 ? (size_t)4 * M1 : (size_t)8 * M1);
    const float* bias = (MODE == 0) ? (z == 0 ? ba : (z == 1 ? bb2 : bc)) : ba;
    __half* Ch = (MODE == 0) ? (z == 0 ? g_qh : (z == 1 ? g_kh : g_vh)) : nullptr;
    float* Cf = (MODE == 1) ? g_x2 : (MODE == 2) ? g_act : (MODE == 3) ? extC : nullptr;
    const float* R = (MODE == 1) ? extRes : (MODE == 3) ? g_x2 : nullptr;

    const int tid  = threadIdx.x;
    const int lane = tid & 31;
    const int wid  = tid >> 5;
    const int mw0  = (wid >> 2) * 64;
    const int nw0  = (wid & 3) * 32;
    const int rowBase = blockIdx.y * 128;
    const int colBase = blockIdx.x * 128;
    const uint32_t dsmb = smem_u32(dsm);

    const int arow = tid >> 2;
    const int acol = tid & 3;
    const int brow = tid >> 5;
    const int bcol = tid & 31;
    const float* Asrc0 = A + (size_t)(rowBase + arow) * K + acol * 4;
    const float* Asrc1 = Asrc0 + (size_t)64 * K;
    const float* Bsrc0 = W + (size_t)brow * N + colBase + bcol * 4;
    const float* Bsrc1 = Bsrc0 + (size_t)8 * N;
    const uint32_t adst0 = arow * 80 + acol * 16;
    const uint32_t adst1 = (arow + 64) * 80 + acol * 16;
    const uint32_t bdst0 = 10240 + brow * 544 + bcol * 16;
    const uint32_t bdst1 = 10240 + (brow + 8) * 544 + bcol * 16;

    float acc[4][4][4];
#pragma unroll
    for (int i = 0; i < 4; i++)
#pragma unroll
        for (int j = 0; j < 4; j++)
#pragma unroll
            for (int c = 0; c < 4; c++) acc[i][j][c] = 0.0f;

    auto issue = [&](int s, int c) {
        const uint32_t st = dsmb + s * STAGE_BYTES;
        const size_t k0 = (size_t)(c << 4);
        cpa16(st + adst0, Asrc0 + k0);
        cpa16(st + adst1, Asrc1 + k0);
        cpa16(st + bdst0, Bsrc0 + k0 * N);
        cpa16(st + bdst1, Bsrc1 + k0 * N);
    };

    issue(0, 0); CP_COMMIT();
    issue(1, 1); CP_COMMIT();

    const int nkt = K >> 4;
    for (int kt = 0; kt < nkt; kt++) {
        CP_WAIT1();
        __syncthreads();
        const int s = kt % 3;
        const uint32_t ab = dsmb + s * STAGE_BYTES;
        const uint32_t* Bsu = (const uint32_t*)(dsm + s * STAGE_BYTES + 10240);

#pragma unroll
        for (int sub = 0; sub < 16; sub += 8) {
            uint32_t a[4][4];
#pragma unroll
            for (int i = 0; i < 4; i++) {
                const uint32_t addr = ab + (mw0 + i * 16 + (lane & 15)) * 80
                                    + (sub + ((lane >> 4) << 2)) * 4;
                LDMATRIX_X4(a[i][0], a[i][1], a[i][2], a[i][3], addr);
            }
            const int lr = lane >> 2;
            const int lc = lane & 3;
#pragma unroll
            for (int j = 0; j < 4; j++) {
                const int nn = nw0 + j * 8 + lr;
                uint32_t bfr[2];
                bfr[0] = Bsu[(sub + lc) * 136 + nn];
                bfr[1] = Bsu[(sub + lc + 4) * 136 + nn];
#pragma unroll
                for (int i = 0; i < 4; i++)
                    mma_tf32(acc[i][j], a[i], bfr);
            }
        }

        if (kt + 2 < nkt) issue((kt + 2) % 3, kt + 2);
        CP_COMMIT();
    }

    // epilogue
    const int lr = lane >> 2;
    const int lc = lane & 3;
#pragma unroll
    for (int i = 0; i < 4; i++) {
        const int r0 = rowBase + mw0 + i * 16 + lr;
#pragma unroll
        for (int j = 0; j < 4; j++) {
            const int c0 = colBase + nw0 + j * 8 + 2 * lc;
            const float b0v = bias[c0], b1v = bias[c0 + 1];
            float v00 = acc[i][j][0] + b0v;
            float v01 = acc[i][j][1] + b1v;
            float v10 = acc[i][j][2] + b0v;
            float v11 = acc[i][j][3] + b1v;
            if (MODE == 2) {
                v00 = roundtf(0.5f * v00 * (1.0f + erff(v00 * 0.70710678118654752f)));
                v01 = roundtf(0.5f * v01 * (1.0f + erff(v01 * 0.70710678118654752f)));
                v10 = roundtf(0.5f * v10 * (1.0f + erff(v10 * 0.70710678118654752f)));
                v11 = roundtf(0.5f * v11 * (1.0f + erff(v11 * 0.70710678118654752f)));
            }
            if (MODE == 0) {
                *(uint32_t*)(Ch + (size_t)r0 * N + c0)       = pack2(v00, v01);
                *(uint32_t*)(Ch + (size_t)(r0 + 8) * N + c0) = pack2(v10, v11);
            } else {
                if (MODE == 1 || MODE == 3) {
                    const float2 r0v = *(const float2*)(R + (size_t)r0 * N + c0);
                    const float2 r1v = *(const float2*)(R + (size_t)(r0 + 8) * N + c0);
                    v00 += r0v.x; v01 += r0v.y;
                    v10 += r1v.x; v11 += r1v.y;
                }
                float2 o0; o0.x = v00; o0.y = v01;
                float2 o1; o1.x = v10; o1.y = v11;
                *(float2*)(Cf + (size_t)r0 * N + c0) = o0;
                *(float2*)(Cf + (size_t)(r0 + 8) * N + c0) = o1;
            }
        }
    }
}

// ---------------- Flash attention: fp16 m16n8k16, cp.async, register P ------------
// (round-12 kernel; reads fp16 q/k/v, writes tf32-rounded fp32 ctx)
__global__ __launch_bounds__(128) void fa_kernel() {
    __shared__ __align__(16) char fsm[2 * 18432];   // per stage: K 9216B + V 9216B
    const uint32_t fab = smem_u32(fsm);

    const int bh = blockIdx.y;
    const int b  = bh >> 4, h = bh & 15;
    const int qBase = blockIdx.x * 64;
    const int tid  = threadIdx.x;
    const int lane = tid & 31;
    const int w    = tid >> 5;
    const int lr   = lane >> 2;
    const int lc   = lane & 3;
    const int qrow = qBase + w * 16;

    const __half* qb = g_qh + (size_t)b * SEQ * DMODEL + h * HDIM;
    const __half* kb = g_kh + (size_t)b * SEQ * DMODEL + h * HDIM;
    const __half* vb = g_vh + (size_t)b * SEQ * DMODEL + h * HDIM;

    const __half2 s8 = __float2half2_rn(0.125f);
    uint32_t aq[4][4];
#pragma unroll
    for (int s = 0; s < 4; s++) {
        const __half* p0 = qb + (size_t)(qrow + lr) * DMODEL + s * 16 + 2 * lc;
        const __half* p1 = qb + (size_t)(qrow + lr + 8) * DMODEL + s * 16 + 2 * lc;
        __half2 x0 = __hmul2(*(const __half2*)p0, s8);
        __half2 x1 = __hmul2(*(const __half2*)p1, s8);
        __half2 x2 = __hmul2(*(const __half2*)(p0 + 8), s8);
        __half2 x3 = __hmul2(*(const __half2*)(p1 + 8), s8);
        aq[s][0] = *(uint32_t*)&x0; aq[s][1] = *(uint32_t*)&x1;
        aq[s][2] = *(uint32_t*)&x2; aq[s][3] = *(uint32_t*)&x3;
    }

    auto issue = [&](int kt2) {
        const uint32_t st = fab + (kt2 & 1) * 18432;
        const __half* kbt = kb + (size_t)kt2 * 64 * DMODEL;
        const __half* vbt = vb + (size_t)kt2 * 64 * DMODEL;
#pragma unroll
        for (int i = 0; i < 4; i++) {
            const int c = tid + 128 * i;
            const int r = c >> 3, ch = c & 7;
            cpa16(st + r * 144 + ch * 16,        kbt + (size_t)r * DMODEL + ch * 8);
            cpa16(st + 9216 + r * 144 + ch * 16, vbt + (size_t)r * DMODEL + ch * 8);
        }
    };

    float m0 = -INFINITY, m1 = -INFINITY, l0 = 0.0f, l1 = 0.0f;
    float oacc[8][4];
#pragma unroll
    for (int j = 0; j < 8; j++)
#pragma unroll
        for (int c = 0; c < 4; c++) oacc[j][c] = 0.0f;

    issue(0); CP_COMMIT();

    for (int kt = 0; kt < SEQ / 64; kt++) {
        CP_WAIT0();
        __syncthreads();
        if (kt + 1 < SEQ / 64) { issue(kt + 1); CP_COMMIT(); }
        const uint32_t ksb = fab + (kt & 1) * 18432;
        const uint32_t vsb = ksb + 9216;

        float sacc[8][4];
#pragma unroll
        for (int j = 0; j < 8; j++)
#pragma unroll
            for (int c = 0; c < 4; c++) sacc[j][c] = 0.0f;
#pragma unroll
        for (int j = 0; j < 8; j++) {
            uint32_t bk[8];
#pragma unroll
            for (int sp = 0; sp < 2; sp++) {
                const uint32_t addr = ksb + (8 * j + (lane & 7)) * 144
                                    + (4 * sp + (lane >> 3)) * 16;
                LDMATRIX_X4(bk[sp * 4], bk[sp * 4 + 1], bk[sp * 4 + 2], bk[sp * 4 + 3], addr);
            }
#pragma unroll
            for (int s = 0; s < 4; s++)
                mma_f16(sacc[j], aq[s], &bk[s * 2]);
        }

        float t0 = -INFINITY, t1 = -INFINITY;
#pragma unroll
        for (int j = 0; j < 8; j++) {
            t0 = fmaxf(t0, fmaxf(sacc[j][0], sacc[j][1]));
            t1 = fmaxf(t1, fmaxf(sacc[j][2], sacc[j][3]));
        }
        t0 = fmaxf(t0, __shfl_xor_sync(0xffffffffu, t0, 1));
        t0 = fmaxf(t0, __shfl_xor_sync(0xffffffffu, t0, 2));
        t1 = fmaxf(t1, __shfl_xor_sync(0xffffffffu, t1, 1));
        t1 = fmaxf(t1, __shfl_xor_sync(0xffffffffu, t1, 2));
        const float nm0 = fmaxf(m0, t0);
        const float nm1 = fmaxf(m1, t1);
        const float al0 = fexp(m0 - nm0);
        const float al1 = fexp(m1 - nm1);
        m0 = nm0; m1 = nm1;
        float s0 = 0.0f, s1 = 0.0f;
#pragma unroll
        for (int j = 0; j < 8; j++) {
            sacc[j][0] = fexp(sacc[j][0] - m0);
            sacc[j][1] = fexp(sacc[j][1] - m0);
            sacc[j][2] = fexp(sacc[j][2] - m1);
            sacc[j][3] = fexp(sacc[j][3] - m1);
            s0 += sacc[j][0] + sacc[j][1];
            s1 += sacc[j][2] + sacc[j][3];
        }
        s0 += __shfl_xor_sync(0xffffffffu, s0, 1);
        s0 += __shfl_xor_sync(0xffffffffu, s0, 2);
        s1 += __shfl_xor_sync(0xffffffffu, s1, 1);
        s1 += __shfl_xor_sync(0xffffffffu, s1, 2);
        l0 = l0 * al0 + s0;
        l1 = l1 * al1 + s1;
#pragma unroll
        for (int j = 0; j < 8; j++) {
            oacc[j][0] *= al0; oacc[j][1] *= al0;
            oacc[j][2] *= al1; oacc[j][3] *= al1;
        }

        uint32_t ap[4][4];
#pragma unroll
        for (int s = 0; s < 4; s++) {
            ap[s][0] = pack2(sacc[2 * s][0], sacc[2 * s][1]);
            ap[s][1] = pack2(sacc[2 * s][2], sacc[2 * s][3]);
            ap[s][2] = pack2(sacc[2 * s + 1][0], sacc[2 * s + 1][1]);
            ap[s][3] = pack2(sacc[2 * s + 1][2], sacc[2 * s + 1][3]);
        }

#pragma unroll
        for (int s = 0; s < 4; s++) {
#pragma unroll
            for (int jp = 0; jp < 4; jp++) {
                uint32_t bv4[4];
                const uint32_t addr = vsb + (16 * s + (lane & 15)) * 144
                                    + (2 * jp + (lane >> 4)) * 16;
                LDMATRIX_X4_T(bv4[0], bv4[1], bv4[2], bv4[3], addr);
                mma_f16(oacc[2 * jp],     ap[s], &bv4[0]);
                mma_f16(oacc[2 * jp + 1], ap[s], &bv4[2]);
            }
        }
    }

    // epilogue: normalize, store ctx fp32 (tf32-rounded: feeds tf32 AO GEMM)
    const float inv0 = 1.0f / l0;
    const float inv1 = 1.0f / l1;
    float* crow0 = g_ctx + (size_t)(b * SEQ + qrow + lr) * DMODEL + h * HDIM;
    float* crow1 = g_ctx + (size_t)(b * SEQ + qrow + lr + 8) * DMODEL + h * HDIM;
#pragma unroll
    for (int j = 0; j < 8; j++) {
        float2 o0; o0.x = roundtf(oacc[j][0] * inv0); o0.y = roundtf(oacc[j][1] * inv0);
        float2 o1; o1.x = roundtf(oacc[j][2] * inv1); o1.y = roundtf(oacc[j][3] * inv1);
        *(float2*)(crow0 + j * 8 + 2 * lc) = o0;
        *(float2*)(crow1 + j * 8 + 2 * lc) = o1;
    }
}

// ---------------- launcher -------------------------------------------------------
extern "C" void kernel_launch(void* const* d_in, const int* in_sizes, int n_in,
                              void* d_out, int out_size) {
    const float* x   = (const float*)d_in[0];
    const float* Wq  = (const float*)d_in[1];
    const float* bq  = (const float*)d_in[2];
    const float* Wk  = (const float*)d_in[3];
    const float* bk  = (const float*)d_in[4];
    const float* Wv  = (const float*)d_in[5];
    const float* bv  = (const float*)d_in[6];
    const float* Wo  = (const float*)d_in[7];
    const float* bo  = (const float*)d_in[8];
    const float* W1  = (const float*)d_in[9];
    const float* b1  = (const float*)d_in[10];
    const float* W2  = (const float*)d_in[11];
    const float* b2  = (const float*)d_in[12];
    const float* g1  = (const float*)d_in[13];
    const float* be1 = (const float*)d_in[14];
    const float* g2  = (const float*)d_in[15];
    const float* be2 = (const float*)d_in[16];
    float* out = (float*)d_out;

    cudaFuncSetAttribute(gemm_cp_kernel<0>, cudaFuncAttributeMaxDynamicSharedMemorySize, GEMM_DSMEM);
    cudaFuncSetAttribute(gemm_cp_kernel<1>, cudaFuncAttributeMaxDynamicSharedMemorySize, GEMM_DSMEM);
    cudaFuncSetAttribute(gemm_cp_kernel<2>, cudaFuncAttributeMaxDynamicSharedMemorySize, GEMM_DSMEM);
    cudaFuncSetAttribute(gemm_cp_kernel<3>, cudaFuncAttributeMaxDynamicSharedMemorySize, GEMM_DSMEM);

    const dim3 gQKV(DMODEL / 128, MTOK / 128, 3);
    const dim3 gD(DMODEL / 128, MTOK / 128);
    const dim3 gF(FFDIM / 128, MTOK / 128);

    wconv_kernel<<<12 * M1 / 1024, 256>>>(Wq, Wk, Wv, Wo, W1, W2);

    // --- attention block ---
    ln_kernel<0><<<MTOK, 256>>>(x, g1, be1);                                   // h (tf32 fp32)
    gemm_cp_kernel<0><<<gQKV, 256, GEMM_DSMEM>>>(bq, bk, bv, nullptr, nullptr); // q,k,v (fp16)
    fa_kernel<<<dim3(SEQ / 64, BATCH * NHEAD), 128>>>();                        // ctx (tf32 fp32)
    gemm_cp_kernel<1><<<gD, 256, GEMM_DSMEM>>>(bo, bo, bo, nullptr, (float*)x); // x2 (fp32)

    // --- FFN block ---
    ln_kernel<1><<<MTOK, 256>>>(nullptr, g2, be2);                              // h (tf32 fp32)
    gemm_cp_kernel<2><<<gF, 256, GEMM_DSMEM>>>(b1, b1, b1, nullptr, nullptr);   // act (tf32 fp32)
    gemm_cp_kernel<3><<<gD, 256, GEMM_DSMEM>>>(b2, b2, b2, out, nullptr);       // out (fp32)
}

// round 14
// speedup vs baseline: 2.1333x; 1.7933x over previous
#include <cuda_runtime.h>
#include <cuda_fp16.h>
#include <math.h>
#include <stdint.h>

// Problem constants
#define DMODEL 1024
#define MTOK   8192      // B*S
#define FFDIM  4096
#define NHEAD  16
#define HDIM   64
#define SEQ    1024
#define BATCH  8

#define GSTAGE 35840                 // A: 128x144B (18432) + B: 64x272B (17408)
#define GEMM_DSMEM (3 * GSTAGE)
#define M1 (1024 * 1024)

// ---------------- scratch (device globals) ---------------------------------------
__device__ __half g_h   [MTOK * DMODEL];  // LN out
__device__ __half g_qh  [MTOK * DMODEL];
__device__ __half g_kh  [MTOK * DMODEL];
__device__ __half g_vh  [MTOK * DMODEL];
__device__ __half g_ctxh[MTOK * DMODEL];  // FA out
__device__ float  g_x2  [MTOK * DMODEL];  // residual stream after attention (fp32)
__device__ __half g_act [MTOK * FFDIM];   // FFN intermediate
// fp16 K-major weights: [0:Wq][1M:Wk][2M:Wv][3M:Wo][4M:W1][8M:W2]
__device__ __half g_wh[12 * M1];

// ---------------- helpers ---------------------------------------------------------
__device__ __forceinline__ uint32_t pack2(float a, float b) {
    __half2 h = __floats2half2_rn(a, b);
    return *reinterpret_cast<uint32_t*>(&h);
}

// fast exp on fma pipe (softmax args <= 0); rel err ~2e-6
__device__ __forceinline__ float fexp(float x) {
    x = fmaxf(x, -80.0f);
    const float y = x * 1.4426950408889634f;
    const float t = y + 12582912.0f;
    const int   n = __float_as_int(t) - 0x4B400000;
    const float f = y - (t - 12582912.0f);
    float p =          1.3333558e-3f;
    p = fmaf(p, f, 9.6181291e-3f);
    p = fmaf(p, f, 5.5504109e-2f);
    p = fmaf(p, f, 2.4022651e-1f);
    p = fmaf(p, f, 6.9314718e-1f);
    p = fmaf(p, f, 1.0f);
    return p * __int_as_float((n + 127) << 23);
}

__device__ __forceinline__ void mma_f16(float* d, const uint32_t* a, const uint32_t* b) {
    asm volatile(
        "mma.sync.aligned.m16n8k16.row.col.f32.f16.f16.f32 "
        "{%0,%1,%2,%3}, {%4,%5,%6,%7}, {%8,%9}, {%0,%1,%2,%3};"
        : "+f"(d[0]), "+f"(d[1]), "+f"(d[2]), "+f"(d[3])
        : "r"(a[0]), "r"(a[1]), "r"(a[2]), "r"(a[3]), "r"(b[0]), "r"(b[1]));
}

__device__ __forceinline__ uint32_t smem_u32(const void* p) {
    uint32_t a;
    asm("{ .reg .u64 t; cvta.to.shared.u64 t, %1; cvt.u32.u64 %0, t; }" : "=r"(a) : "l"(p));
    return a;
}
__device__ __forceinline__ void cpa16(uint32_t dst, const void* src) {
    asm volatile("cp.async.cg.shared.global [%0], [%1], 16;" :: "r"(dst), "l"(src));
}
#define CP_COMMIT() asm volatile("cp.async.commit_group;" ::: "memory")
#define CP_WAIT1()  asm volatile("cp.async.wait_group 1;" ::: "memory")
#define CP_WAIT0()  asm volatile("cp.async.wait_group 0;" ::: "memory")

#define LDMATRIX_X4(r0, r1, r2, r3, addr) \
    asm volatile("ldmatrix.sync.aligned.m8n8.x4.shared.b16 {%0,%1,%2,%3}, [%4];" \
        : "=r"(r0), "=r"(r1), "=r"(r2), "=r"(r3) : "r"(addr))
#define LDMATRIX_X4_T(r0, r1, r2, r3, addr) \
    asm volatile("ldmatrix.sync.aligned.m8n8.x4.trans.shared.b16 {%0,%1,%2,%3}, [%4];" \
        : "=r"(r0), "=r"(r1), "=r"(r2), "=r"(r3) : "r"(addr))

// ---------------- weight convert: fp32 -> fp16, K-major (coalesced) ---------------
__global__ __launch_bounds__(256) void wconv_kernel(
    const float* __restrict__ Wq, const float* __restrict__ Wk,
    const float* __restrict__ Wv, const float* __restrict__ Wo,
    const float* __restrict__ W1, const float* __restrict__ W2) {
    const size_t i8 = ((size_t)blockIdx.x * 256 + threadIdx.x) * 8;
    const float* src;
    size_t base;
    if      (i8 < 1 * M1) { src = Wq; base = 0; }
    else if (i8 < 2 * M1) { src = Wk; base = 1 * M1; }
    else if (i8 < 3 * M1) { src = Wv; base = 2 * M1; }
    else if (i8 < 4 * M1) { src = Wo; base = 3 * M1; }
    else if (i8 < 8 * M1) { src = W1; base = 4 * M1; }
    else                  { src = W2; base = 8 * M1; }
    const float4 a = *(const float4*)(src + (i8 - base));
    const float4 b = *(const float4*)(src + (i8 - base) + 4);
    uint4 o;
    o.x = pack2(a.x, a.y); o.y = pack2(a.z, a.w);
    o.z = pack2(b.x, b.y); o.w = pack2(b.z, b.w);
    *(uint4*)(g_wh + i8) = o;
}

// ---------------- LayerNorm: fp32 in -> fp16 out ----------------------------------
template <int SRC>   // 0: external x, 1: g_x2
__global__ __launch_bounds__(256) void ln_kernel(const float* __restrict__ xext,
                                                 const float* __restrict__ g,
                                                 const float* __restrict__ be) {
    const float* src = SRC ? g_x2 : xext;
    __shared__ float s1[256], s2[256];
    const int row = blockIdx.x;
    const int tid = threadIdx.x;
    const float4 v = ((const float4*)(src + (size_t)row * DMODEL))[tid];
    float sum = v.x + v.y + v.z + v.w;
    float sq  = v.x*v.x + v.y*v.y + v.z*v.z + v.w*v.w;
    s1[tid] = sum; s2[tid] = sq;
    __syncthreads();
    for (int s = 128; s > 0; s >>= 1) {
        if (tid < s) { s1[tid] += s1[tid + s]; s2[tid] += s2[tid + s]; }
        __syncthreads();
    }
    const float mean = s1[0] * (1.0f / DMODEL);
    const float var  = s2[0] * (1.0f / DMODEL) - mean * mean;
    const float rs   = rsqrtf(var + 1e-5f);
    const float4 gv = ((const float4*)g)[tid];
    const float4 bv = ((const float4*)be)[tid];
    uint2 o;
    o.x = pack2((v.x - mean) * rs * gv.x + bv.x, (v.y - mean) * rs * gv.y + bv.y);
    o.y = pack2((v.z - mean) * rs * gv.z + bv.z, (v.w - mean) * rs * gv.w + bv.w);
    *(uint2*)(g_h + (size_t)row * DMODEL + tid * 4) = o;
}

// ---------------- Dense GEMM: fp16 m16n8k16, BK=64, ldmatrix.trans B --------------
// MODE 0: QKV (z selects W/bias/dst; fp16 out)   MODE 1: AO (fp32 x2, res ext x)
// MODE 2: FFN1 (GELU, fp16 out)                  MODE 3: FFN2 (fp32 ext out, res x2)
// Tile 128x128, 8 warps (2m x 4n), warp tile 64x32. A [128m][64k] stride 144B;
// B [64k][128n] stride 272B (K-major, coalesced 256B row reads).
template <int MODE>
__global__ __launch_bounds__(256) void gemm_h_kernel(
    const float* __restrict__ ba, const float* __restrict__ bb2, const float* __restrict__ bc,
    float* __restrict__ extC, const float* __restrict__ extRes) {
    extern __shared__ __align__(16) char dsm[];
    constexpr int N = (MODE == 2) ? 4096 : 1024;
    constexpr int K = (MODE == 3) ? 4096 : 1024;

    const __half* A = (MODE == 0 || MODE == 2) ? g_h : (MODE == 1 ? g_ctxh : g_act);
    const int z = (MODE == 0) ? blockIdx.z : 0;
    const __half* W = g_wh + (MODE == 0 ? (size_t)z * M1
                             : MODE == 1 ? (size_t)3 * M1
                             : MODE == 2 ? (size_t)4 * M1 : (size_t)8 * M1);
    const float* bias = (MODE == 0) ? (z == 0 ? ba : (z == 1 ? bb2 : bc)) : ba;
    __half* Ch = (MODE == 0) ? (z == 0 ? g_qh : (z == 1 ? g_kh : g_vh))
               : (MODE == 2) ? g_act : nullptr;
    float* Cf = (MODE == 1) ? g_x2 : (MODE == 3) ? extC : nullptr;
    const float* R = (MODE == 1) ? extRes : (MODE == 3) ? g_x2 : nullptr;

    const int tid  = threadIdx.x;
    const int lane = tid & 31;
    const int wid  = tid >> 5;
    const int mw0  = (wid >> 2) * 64;
    const int nw0  = (wid & 3) * 32;
    const int rowBase = blockIdx.y * 128;
    const int colBase = blockIdx.x * 128;
    const uint32_t dsmb = smem_u32(dsm);

    float acc[4][4][4];
#pragma unroll
    for (int i = 0; i < 4; i++)
#pragma unroll
        for (int j = 0; j < 4; j++)
#pragma unroll
            for (int c = 0; c < 4; c++) acc[i][j][c] = 0.0f;

    // staging: A 1024 chunks (row c>>3, ch c&7), B 1024 chunks (row c>>4, ch c&15)
    auto issue = [&](int s, int c) {
        const uint32_t st = dsmb + s * GSTAGE;
        const int k0 = c << 6;
#pragma unroll
        for (int i = 0; i < 4; i++) {
            const int ca = tid + 256 * i;
            const int ar = ca >> 3, ach = ca & 7;
            cpa16(st + ar * 144 + ach * 16,
                  A + (size_t)(rowBase + ar) * K + k0 + ach * 8);
            const int br = ca >> 4, bch = ca & 15;
            cpa16(st + 18432 + br * 272 + bch * 16,
                  W + (size_t)(k0 + br) * N + colBase + bch * 8);
        }
    };

    issue(0, 0); CP_COMMIT();
    issue(1, 1); CP_COMMIT();

    const int nkt = K >> 6;
    for (int kt = 0; kt < nkt; kt++) {
        CP_WAIT1();
        __syncthreads();
        const int sg = kt % 3;
        const uint32_t ab = dsmb + sg * GSTAGE;
        const uint32_t bb = ab + 18432;

#pragma unroll
        for (int s = 0; s < 4; s++) {          // k16 substeps
            uint32_t a[4][4];
#pragma unroll
            for (int i = 0; i < 4; i++) {
                const uint32_t addr = ab + (mw0 + 16 * i + (lane & 15)) * 144
                                    + (2 * s + (lane >> 4)) * 16;
                LDMATRIX_X4(a[i][0], a[i][1], a[i][2], a[i][3], addr);
            }
#pragma unroll
            for (int jp = 0; jp < 2; jp++) {   // n16 pairs
                uint32_t bv4[4];
                const uint32_t addr = bb + (16 * s + (lane & 15)) * 272
                                    + ((nw0 >> 3) + 2 * jp + (lane >> 4)) * 16;
                LDMATRIX_X4_T(bv4[0], bv4[1], bv4[2], bv4[3], addr);
#pragma unroll
                for (int i = 0; i < 4; i++) {
                    mma_f16(acc[i][2 * jp],     a[i], &bv4[0]);
                    mma_f16(acc[i][2 * jp + 1], a[i], &bv4[2]);
                }
            }
        }

        if (kt + 2 < nkt) issue((kt + 2) % 3, kt + 2);
        CP_COMMIT();
    }

    // epilogue
    const int lr = lane >> 2;
    const int lc = lane & 3;
#pragma unroll
    for (int i = 0; i < 4; i++) {
        const int r0 = rowBase + mw0 + i * 16 + lr;
#pragma unroll
        for (int j = 0; j < 4; j++) {
            const int c0 = colBase + nw0 + j * 8 + 2 * lc;
            const float b0v = bias[c0], b1v = bias[c0 + 1];
            float v00 = acc[i][j][0] + b0v;
            float v01 = acc[i][j][1] + b1v;
            float v10 = acc[i][j][2] + b0v;
            float v11 = acc[i][j][3] + b1v;
            if (MODE == 2) {
                v00 = 0.5f * v00 * (1.0f + erff(v00 * 0.70710678118654752f));
                v01 = 0.5f * v01 * (1.0f + erff(v01 * 0.70710678118654752f));
                v10 = 0.5f * v10 * (1.0f + erff(v10 * 0.70710678118654752f));
                v11 = 0.5f * v11 * (1.0f + erff(v11 * 0.70710678118654752f));
            }
            if (MODE == 0 || MODE == 2) {
                *(uint32_t*)(Ch + (size_t)r0 * N + c0)       = pack2(v00, v01);
                *(uint32_t*)(Ch + (size_t)(r0 + 8) * N + c0) = pack2(v10, v11);
            } else {
                const float2 r0v = *(const float2*)(R + (size_t)r0 * N + c0);
                const float2 r1v = *(const float2*)(R + (size_t)(r0 + 8) * N + c0);
                float2 o0; o0.x = v00 + r0v.x; o0.y = v01 + r0v.y;
                float2 o1; o1.x = v10 + r1v.x; o1.y = v11 + r1v.y;
                *(float2*)(Cf + (size_t)r0 * N + c0) = o0;
                *(float2*)(Cf + (size_t)(r0 + 8) * N + c0) = o1;
            }
        }
    }
}

// ---------------- Flash attention: fp16 m16n8k16, cp.async, register P ------------
__global__ __launch_bounds__(128) void fa_kernel() {
    __shared__ __align__(16) char fsm[2 * 18432];   // per stage: K 9216B + V 9216B
    const uint32_t fab = smem_u32(fsm);

    const int bh = blockIdx.y;
    const int b  = bh >> 4, h = bh & 15;
    const int qBase = blockIdx.x * 64;
    const int tid  = threadIdx.x;
    const int lane = tid & 31;
    const int w    = tid >> 5;
    const int lr   = lane >> 2;
    const int lc   = lane & 3;
    const int qrow = qBase + w * 16;

    const __half* qb = g_qh + (size_t)b * SEQ * DMODEL + h * HDIM;
    const __half* kb = g_kh + (size_t)b * SEQ * DMODEL + h * HDIM;
    const __half* vb = g_vh + (size_t)b * SEQ * DMODEL + h * HDIM;

    const __half2 s8 = __float2half2_rn(0.125f);
    uint32_t aq[4][4];
#pragma unroll
    for (int s = 0; s < 4; s++) {
        const __half* p0 = qb + (size_t)(qrow + lr) * DMODEL + s * 16 + 2 * lc;
        const __half* p1 = qb + (size_t)(qrow + lr + 8) * DMODEL + s * 16 + 2 * lc;
        __half2 x0 = __hmul2(*(const __half2*)p0, s8);
        __half2 x1 = __hmul2(*(const __half2*)p1, s8);
        __half2 x2 = __hmul2(*(const __half2*)(p0 + 8), s8);
        __half2 x3 = __hmul2(*(const __half2*)(p1 + 8), s8);
        aq[s][0] = *(uint32_t*)&x0; aq[s][1] = *(uint32_t*)&x1;
        aq[s][2] = *(uint32_t*)&x2; aq[s][3] = *(uint32_t*)&x3;
    }

    auto issue = [&](int kt2) {
        const uint32_t st = fab + (kt2 & 1) * 18432;
        const __half* kbt = kb + (size_t)kt2 * 64 * DMODEL;
        const __half* vbt = vb + (size_t)kt2 * 64 * DMODEL;
#pragma unroll
        for (int i = 0; i < 4; i++) {
            const int c = tid + 128 * i;
            const int r = c >> 3, ch = c & 7;
            cpa16(st + r * 144 + ch * 16,        kbt + (size_t)r * DMODEL + ch * 8);
            cpa16(st + 9216 + r * 144 + ch * 16, vbt + (size_t)r * DMODEL + ch * 8);
        }
    };

    float m0 = -INFINITY, m1 = -INFINITY, l0 = 0.0f, l1 = 0.0f;
    float oacc[8][4];
#pragma unroll
    for (int j = 0; j < 8; j++)
#pragma unroll
        for (int c = 0; c < 4; c++) oacc[j][c] = 0.0f;

    issue(0); CP_COMMIT();

    for (int kt = 0; kt < SEQ / 64; kt++) {
        CP_WAIT0();
        __syncthreads();
        if (kt + 1 < SEQ / 64) { issue(kt + 1); CP_COMMIT(); }
        const uint32_t ksb = fab + (kt & 1) * 18432;
        const uint32_t vsb = ksb + 9216;

        float sacc[8][4];
#pragma unroll
        for (int j = 0; j < 8; j++)
#pragma unroll
            for (int c = 0; c < 4; c++) sacc[j][c] = 0.0f;
#pragma unroll
        for (int j = 0; j < 8; j++) {
            uint32_t bk[8];
#pragma unroll
            for (int sp = 0; sp < 2; sp++) {
                const uint32_t addr = ksb + (8 * j + (lane & 7)) * 144
                                    + (4 * sp + (lane >> 3)) * 16;
                LDMATRIX_X4(bk[sp * 4], bk[sp * 4 + 1], bk[sp * 4 + 2], bk[sp * 4 + 3], addr);
            }
#pragma unroll
            for (int s = 0; s < 4; s++)
                mma_f16(sacc[j], aq[s], &bk[s * 2]);
        }

        float t0 = -INFINITY, t1 = -INFINITY;
#pragma unroll
        for (int j = 0; j < 8; j++) {
            t0 = fmaxf(t0, fmaxf(sacc[j][0], sacc[j][1]));
            t1 = fmaxf(t1, fmaxf(sacc[j][2], sacc[j][3]));
        }
        t0 = fmaxf(t0, __shfl_xor_sync(0xffffffffu, t0, 1));
        t0 = fmaxf(t0, __shfl_xor_sync(0xffffffffu, t0, 2));
        t1 = fmaxf(t1, __shfl_xor_sync(0xffffffffu, t1, 1));
        t1 = fmaxf(t1, __shfl_xor_sync(0xffffffffu, t1, 2));
        const float nm0 = fmaxf(m0, t0);
        const float nm1 = fmaxf(m1, t1);
        const float al0 = fexp(m0 - nm0);
        const float al1 = fexp(m1 - nm1);
        m0 = nm0; m1 = nm1;
        float s0 = 0.0f, s1 = 0.0f;
#pragma unroll
        for (int j = 0; j < 8; j++) {
            sacc[j][0] = fexp(sacc[j][0] - m0);
            sacc[j][1] = fexp(sacc[j][1] - m0);
            sacc[j][2] = fexp(sacc[j][2] - m1);
            sacc[j][3] = fexp(sacc[j][3] - m1);
            s0 += sacc[j][0] + sacc[j][1];
            s1 += sacc[j][2] + sacc[j][3];
        }
        s0 += __shfl_xor_sync(0xffffffffu, s0, 1);
        s0 += __shfl_xor_sync(0xffffffffu, s0, 2);
        s1 += __shfl_xor_sync(0xffffffffu, s1, 1);
        s1 += __shfl_xor_sync(0xffffffffu, s1, 2);
        l0 = l0 * al0 + s0;
        l1 = l1 * al1 + s1;
#pragma unroll
        for (int j = 0; j < 8; j++) {
            oacc[j][0] *= al0; oacc[j][1] *= al0;
            oacc[j][2] *= al1; oacc[j][3] *= al1;
        }

        uint32_t ap[4][4];
#pragma unroll
        for (int s = 0; s < 4; s++) {
            ap[s][0] = pack2(sacc[2 * s][0], sacc[2 * s][1]);
            ap[s][1] = pack2(sacc[2 * s][2], sacc[2 * s][3]);
            ap[s][2] = pack2(sacc[2 * s + 1][0], sacc[2 * s + 1][1]);
            ap[s][3] = pack2(sacc[2 * s + 1][2], sacc[2 * s + 1][3]);
        }

#pragma unroll
        for (int s = 0; s < 4; s++) {
#pragma unroll
            for (int jp = 0; jp < 4; jp++) {
                uint32_t bv4[4];
                const uint32_t addr = vsb + (16 * s + (lane & 15)) * 144
                                    + (2 * jp + (lane >> 4)) * 16;
                LDMATRIX_X4_T(bv4[0], bv4[1], bv4[2], bv4[3], addr);
                mma_f16(oacc[2 * jp],     ap[s], &bv4[0]);
                mma_f16(oacc[2 * jp + 1], ap[s], &bv4[2]);
            }
        }
    }

    // epilogue: normalize, store ctx fp16
    const float inv0 = 1.0f / l0;
    const float inv1 = 1.0f / l1;
    __half* crow0 = g_ctxh + (size_t)(b * SEQ + qrow + lr) * DMODEL + h * HDIM;
    __half* crow1 = g_ctxh + (size_t)(b * SEQ + qrow + lr + 8) * DMODEL + h * HDIM;
#pragma unroll
    for (int j = 0; j < 8; j++) {
        *(uint32_t*)(crow0 + j * 8 + 2 * lc) = pack2(oacc[j][0] * inv0, oacc[j][1] * inv0);
        *(uint32_t*)(crow1 + j * 8 + 2 * lc) = pack2(oacc[j][2] * inv1, oacc[j][3] * inv1);
    }
}

// ---------------- launcher -------------------------------------------------------
extern "C" void kernel_launch(void* const* d_in, const int* in_sizes, int n_in,
                              void* d_out, int out_size) {
    const float* x   = (const float*)d_in[0];
    const float* Wq  = (const float*)d_in[1];
    const float* bq  = (const float*)d_in[2];
    const float* Wk  = (const float*)d_in[3];
    const float* bk  = (const float*)d_in[4];
    const float* Wv  = (const float*)d_in[5];
    const float* bv  = (const float*)d_in[6];
    const float* Wo  = (const float*)d_in[7];
    const float* bo  = (const float*)d_in[8];
    const float* W1  = (const float*)d_in[9];
    const float* b1  = (const float*)d_in[10];
    const float* W2  = (const float*)d_in[11];
    const float* b2  = (const float*)d_in[12];
    const float* g1  = (const float*)d_in[13];
    const float* be1 = (const float*)d_in[14];
    const float* g2  = (const float*)d_in[15];
    const float* be2 = (const float*)d_in[16];
    float* out = (float*)d_out;

    cudaFuncSetAttribute(gemm_h_kernel<0>, cudaFuncAttributeMaxDynamicSharedMemorySize, GEMM_DSMEM);
    cudaFuncSetAttribute(gemm_h_kernel<1>, cudaFuncAttributeMaxDynamicSharedMemorySize, GEMM_DSMEM);
    cudaFuncSetAttribute(gemm_h_kernel<2>, cudaFuncAttributeMaxDynamicSharedMemorySize, GEMM_DSMEM);
    cudaFuncSetAttribute(gemm_h_kernel<3>, cudaFuncAttributeMaxDynamicSharedMemorySize, GEMM_DSMEM);

    const dim3 gQKV(DMODEL / 128, MTOK / 128, 3);
    const dim3 gD(DMODEL / 128, MTOK / 128);
    const dim3 gF(FFDIM / 128, MTOK / 128);

    wconv_kernel<<<6144, 256>>>(Wq, Wk, Wv, Wo, W1, W2);

    // --- attention block ---
    ln_kernel<0><<<MTOK, 256>>>(x, g1, be1);                                    // h (fp16)
    gemm_h_kernel<0><<<gQKV, 256, GEMM_DSMEM>>>(bq, bk, bv, nullptr, nullptr);  // q,k,v (fp16)
    fa_kernel<<<dim3(SEQ / 64, BATCH * NHEAD), 128>>>();                        // ctx (fp16)
    gemm_h_kernel<1><<<gD, 256, GEMM_DSMEM>>>(bo, bo, bo, nullptr, (float*)x);  // x2 (fp32)

    // --- FFN block ---
    ln_kernel<1><<<MTOK, 256>>>(nullptr, g2, be2);                              // h (fp16)
    gemm_h_kernel<2><<<gF, 256, GEMM_DSMEM>>>(b1, b1, b1, nullptr, nullptr);    // act (fp16)
    gemm_h_kernel<3><<<gD, 256, GEMM_DSMEM>>>(b2, b2, b2, out, nullptr);        // out (fp32)
}